// round 17
// baseline (speedup 1.0000x reference)
#include <cuda_runtime.h>
#include <cstdint>

// FPS + gather, bit-exact vs JAX/XLA (distance = fma(dz,dz, fma(dx,dx, rn(dy*dy)))).
// B=8, N=131072, S=4096.
//
// R16 = R14 batch pairing with two fixes:
//  (1) CTA-reduce bfly now starts at off=16 so ALL 32 lanes (incl. lanes
//      16..31, i.e. CTAs with rank c>=16) hold the true CTA key. R14's off=8
//      left lanes 16..31 with 0 -> self-detect injected key 0 for half the
//      CTAs -> inconsistent winners -> rel_err 2.0.
//  (2) slots double-buffered by round parity (key[2][CPB]) -> the fast-CTA
//      one-round-ahead publish can never overwrite a tag a straggler still
//      needs (deadlock-proof).
// Everything else identical to R14: 4 pairs x 32 CTAs, each CTA slices two
// batches (8 pts/thread each); compute+publish A, compute+publish B, then
// detect/finalize A, B (A's L2 latency hides under B's compute). Volatile
// tagged slots, self-detect, coord prefetch on detect, u64 shuffle reduces.

#define NB 8
#define NP 131072
#define NS 4096
#define NPAIR 4
#define CPB 32                 // CTAs per batch
#define NT 512                 // threads per CTA
#define ROUNDS (NS - 1)
#define PPC (NP / CPB)         // 4096 points per CTA per batch
#define PPT 8                  // points per thread per batch

__device__ float4 g_xyz[NB * NP];
struct __align__(2048) BSlots { unsigned long long key[2][CPB]; };
__device__ BSlots g_slots[NB];

__global__ void fps_prep_kernel(const float* __restrict__ pts) {
    if (blockIdx.x == 0 && threadIdx.x < NB * CPB) {
        g_slots[threadIdx.x / CPB].key[0][threadIdx.x % CPB] = 0ull;  // tag 0 < 1
        g_slots[threadIdx.x / CPB].key[1][threadIdx.x % CPB] = 0ull;
    }
    int i = blockIdx.x * blockDim.x + threadIdx.x;
    int stride = gridDim.x * blockDim.x;
    for (; i < NB * NP; i += stride) {
        g_xyz[i] = make_float4(pts[3 * i + 0], pts[3 * i + 1], pts[3 * i + 2], 0.0f);
    }
}

__global__ void __launch_bounds__(NT, 1) fps_main_kernel(float* __restrict__ out) {
    const int bpair = blockIdx.x / CPB;
    const int c     = blockIdx.x % CPB;
    const int bA    = bpair * 2;
    const int bB    = bA + 1;
    const int tid   = threadIdx.x;
    const int lane  = tid & 31;
    const int wid   = tid >> 5;
    const int base  = c * PPC;
    const float4* __restrict__ PA = g_xyz + bA * NP;
    const float4* __restrict__ PB = g_xyz + bB * NP;

    // one-time: 8 points/thread per batch into registers
    float pxA[PPT], pyA[PPT], pzA[PPT], mdA[PPT];
    float pxB[PPT], pyB[PPT], pzB[PPT], mdB[PPT];
#pragma unroll
    for (int j = 0; j < 2; ++j) {
        const int e = j * NT + tid;
#pragma unroll
        for (int k = 0; k < 4; ++k) {
            float4 qa = PA[base + e * 4 + k];
            float4 qb = PB[base + e * 4 + k];
            pxA[j*4+k] = qa.x; pyA[j*4+k] = qa.y; pzA[j*4+k] = qa.z;
            pxB[j*4+k] = qb.x; pyB[j*4+k] = qb.y; pzB[j*4+k] = qb.z;
        }
    }
#pragma unroll
    for (int i = 0; i < PPT; ++i) { mdA[i] = 1e10f; mdB[i] = 1e10f; }

    __shared__ unsigned long long s_kA[NT / 32];
    __shared__ unsigned long long s_kB[NT / 32];
    __shared__ float s_winA[3], s_winB[3];

    // selection 0 is always index 0 (per batch)
    float4 a0 = PA[0], b0 = PB[0];
    float lxA = a0.x, lyA = a0.y, lzA = a0.z;
    float lxB = b0.x, lyB = b0.y, lzB = b0.z;
    if (c == 0 && tid == 0) {
        out[(bA * NS + 0) * 3 + 0] = lxA;
        out[(bA * NS + 0) * 3 + 1] = lyA;
        out[(bA * NS + 0) * 3 + 2] = lzA;
        out[(bB * NS + 0) * 3 + 0] = lxB;
        out[(bB * NS + 0) * 3 + 1] = lyB;
        out[(bB * NS + 0) * 3 + 2] = lzB;
    }

    const int tb = base + tid * 4;

    for (int r = 0; r < ROUNDS; ++r) {
        const unsigned long long tag = (unsigned long long)(r + 1);  // 13 bits
        const int par = r & 1;
        unsigned long long* __restrict__ slotsA = g_slots[bA].key[par];
        unsigned long long* __restrict__ slotsB = g_slots[bB].key[par];

        // ---------- batch A: compute + warp reduce ----------
        float bvA = -1.0f; int biA = 0;
#pragma unroll
        for (int j = 0; j < 2; ++j) {
#pragma unroll
            for (int k = 0; k < 4; ++k) {
                const int t   = j * 4 + k;
                const int idx = tb + j * (NT * 4) + k;
                // FROZEN arithmetic (rel_err 0.0)
                float dx = __fsub_rn(pxA[t], lxA);
                float dy = __fsub_rn(pyA[t], lyA);
                float dz = __fsub_rn(pzA[t], lzA);
                float d  = __fmaf_rn(dz, dz, __fmaf_rn(dx, dx, __fmul_rn(dy, dy)));
                float m  = fminf(mdA[t], d);
                mdA[t] = m;
                if (m > bvA) { bvA = m; biA = idx; }
            }
        }
        unsigned long long wkA =
            ((unsigned long long)__float_as_uint(bvA) << 17) |
            (unsigned)(0x1FFFF - biA);
#pragma unroll
        for (int off = 16; off > 0; off >>= 1) {
            unsigned long long ok = __shfl_down_sync(0xffffffffu, wkA, off);
            if (ok > wkA) wkA = ok;
        }
        if (lane == 0) s_kA[wid] = wkA;

        // ---------- batch B: compute + warp reduce ----------
        float bvB = -1.0f; int biB = 0;
#pragma unroll
        for (int j = 0; j < 2; ++j) {
#pragma unroll
            for (int k = 0; k < 4; ++k) {
                const int t   = j * 4 + k;
                const int idx = tb + j * (NT * 4) + k;
                float dx = __fsub_rn(pxB[t], lxB);
                float dy = __fsub_rn(pyB[t], lyB);
                float dz = __fsub_rn(pzB[t], lzB);
                float d  = __fmaf_rn(dz, dz, __fmaf_rn(dx, dx, __fmul_rn(dy, dy)));
                float m  = fminf(mdB[t], d);
                mdB[t] = m;
                if (m > bvB) { bvB = m; biB = idx; }
            }
        }
        unsigned long long wkB =
            ((unsigned long long)__float_as_uint(bvB) << 17) |
            (unsigned)(0x1FFFF - biB);
#pragma unroll
        for (int off = 16; off > 0; off >>= 1) {
            unsigned long long ok = __shfl_down_sync(0xffffffffu, wkB, off);
            if (ok > wkB) wkB = ok;
        }
        if (lane == 0) s_kB[wid] = wkB;

        __syncthreads();

        if (wid == 0) {
            // ---- CTA reduce + publish A (FULL-WIDTH bfly: all 32 lanes get kkA) ----
            unsigned long long kkA = (lane < 16) ? s_kA[lane] : 0ull;
#pragma unroll
            for (int off = 16; off > 0; off >>= 1) {
                unsigned long long ok = __shfl_xor_sync(0xffffffffu, kkA, off);
                if (ok > kkA) kkA = ok;
            }
            unsigned long long slotA = (kkA << 13) | tag;
            if (lane == 0) {
                asm volatile("st.volatile.global.b64 [%0], %1;"
                             :: "l"(&slotsA[c]), "l"(slotA) : "memory");
            }

            // ---- CTA reduce + publish B ----
            unsigned long long kkB = (lane < 16) ? s_kB[lane] : 0ull;
#pragma unroll
            for (int off = 16; off > 0; off >>= 1) {
                unsigned long long ok = __shfl_xor_sync(0xffffffffu, kkB, off);
                if (ok > kkB) kkB = ok;
            }
            unsigned long long slotB = (kkB << 13) | tag;
            if (lane == 0) {
                asm volatile("st.volatile.global.b64 [%0], %1;"
                             :: "l"(&slotsB[c]), "l"(slotB) : "memory");
            }

            // ---- detect + finalize A (A stores have had B-compute time to land) ----
            {
                unsigned long long k = 0ull;
                float4 w4 = make_float4(0.f, 0.f, 0.f, 0.f);
                bool got = false;
                if (lane == c) {
                    k = slotA; got = true;
                    w4 = PA[0x1FFFF - (int)(kkA & 0x1FFFFull)];   // own slice: L1 hit
                }
                do {
                    if (!got) {
                        asm volatile("ld.volatile.global.b64 %0, [%1];"
                                     : "=l"(k) : "l"(&slotsA[lane]) : "memory");
                        if ((k & 0x1FFFull) == tag) {
                            got = true;
                            w4 = PA[0x1FFFF - (int)((k >> 13) & 0x1FFFFull)];
                        }
                    }
                } while (!__all_sync(0xffffffffu, got));

                unsigned long long mykey = k >> 13, k2 = mykey;
#pragma unroll
                for (int off = 16; off > 0; off >>= 1) {
                    unsigned long long ok = __shfl_xor_sync(0xffffffffu, k2, off);
                    if (ok > k2) k2 = ok;
                }
                unsigned wl = __ffs(__ballot_sync(0xffffffffu, mykey == k2)) - 1u;
                float wx = __shfl_sync(0xffffffffu, w4.x, wl);
                float wy = __shfl_sync(0xffffffffu, w4.y, wl);
                float wz = __shfl_sync(0xffffffffu, w4.z, wl);
                if (lane == 0) {
                    s_winA[0] = wx; s_winA[1] = wy; s_winA[2] = wz;
                    if (c == 0) {
                        out[(bA * NS + r + 1) * 3 + 0] = wx;
                        out[(bA * NS + r + 1) * 3 + 1] = wy;
                        out[(bA * NS + r + 1) * 3 + 2] = wz;
                    }
                }
            }

            // ---- detect + finalize B ----
            {
                unsigned long long k = 0ull;
                float4 w4 = make_float4(0.f, 0.f, 0.f, 0.f);
                bool got = false;
                if (lane == c) {
                    k = slotB; got = true;
                    w4 = PB[0x1FFFF - (int)(kkB & 0x1FFFFull)];
                }
                do {
                    if (!got) {
                        asm volatile("ld.volatile.global.b64 %0, [%1];"
                                     : "=l"(k) : "l"(&slotsB[lane]) : "memory");
                        if ((k & 0x1FFFull) == tag) {
                            got = true;
                            w4 = PB[0x1FFFF - (int)((k >> 13) & 0x1FFFFull)];
                        }
                    }
                } while (!__all_sync(0xffffffffu, got));

                unsigned long long mykey = k >> 13, k2 = mykey;
#pragma unroll
                for (int off = 16; off > 0; off >>= 1) {
                    unsigned long long ok = __shfl_xor_sync(0xffffffffu, k2, off);
                    if (ok > k2) k2 = ok;
                }
                unsigned wl = __ffs(__ballot_sync(0xffffffffu, mykey == k2)) - 1u;
                float wx = __shfl_sync(0xffffffffu, w4.x, wl);
                float wy = __shfl_sync(0xffffffffu, w4.y, wl);
                float wz = __shfl_sync(0xffffffffu, w4.z, wl);
                if (lane == 0) {
                    s_winB[0] = wx; s_winB[1] = wy; s_winB[2] = wz;
                    if (c == 0) {
                        out[(bB * NS + r + 1) * 3 + 0] = wx;
                        out[(bB * NS + r + 1) * 3 + 1] = wy;
                        out[(bB * NS + r + 1) * 3 + 2] = wz;
                    }
                }
            }
        }
        __syncthreads();
        lxA = s_winA[0]; lyA = s_winA[1]; lzA = s_winA[2];
        lxB = s_winB[0]; lyB = s_winB[1]; lzB = s_winB[2];
    }
}

extern "C" void kernel_launch(void* const* d_in, const int* in_sizes, int n_in,
                              void* d_out, int out_size) {
    const float* pts = (const float*)d_in[0];
    float* out = (float*)d_out;
    (void)in_sizes; (void)n_in; (void)out_size;

    fps_prep_kernel<<<512, 256>>>(pts);
    fps_main_kernel<<<NPAIR * CPB, NT>>>(out);
}